// round 1
// baseline (speedup 1.0000x reference)
#include <cuda_runtime.h>

// Problem constants (MoEGate: B=4, S=4096, H=2048, E=64, K=2)
#define NBATCH 4
#define SEQ    4096
#define HID    2048
#define NE     64
#define TOPK   2
#define NTOK   (NBATCH * SEQ)   // 16384

#define TB 64    // tokens per block
#define BK 32    // k-chunk

// Aux-loss accumulators (no allocation allowed -> device globals)
__device__ float g_ssum[NBATCH * NE];
__device__ int   g_cnt [NBATCH * NE];

typedef unsigned long long ull;

__device__ __forceinline__ ull pack2(float lo, float hi) {
    ull r;
    asm("mov.b64 %0, {%1, %2};" : "=l"(r) : "f"(lo), "f"(hi));
    return r;
}
__device__ __forceinline__ void unpack2(ull v, float &lo, float &hi) {
    asm("mov.b64 {%0, %1}, %2;" : "=f"(lo), "=f"(hi) : "l"(v));
}
// packed dual-fp32 FMA: d.lo += a.lo*b.lo ; d.hi += a.hi*b.hi
__device__ __forceinline__ void fma2(ull &d, ull a, ull b) {
    asm("fma.rn.f32x2 %0, %1, %2, %0;" : "+l"(d) : "l"(a), "l"(b));
}

__global__ void zero_acc_kernel() {
    int t = threadIdx.x;
    if (t < NBATCH * NE) { g_ssum[t] = 0.0f; g_cnt[t] = 0; }
}

__global__ __launch_bounds__(256, 2)
void gate_kernel(const float* __restrict__ x, const float* __restrict__ w,
                 float* __restrict__ out)
{
    // smem: staged x/w tiles (transposed to [k][row]), reused as logits buffer
    __shared__ __align__(16) float smraw[2 * BK * (TB + 4)];   // 17408 B
    __shared__ int cnt_s[NE];

    float (*xs)[TB + 4] = (float (*)[TB + 4])smraw;
    float (*ws)[NE + 4] = (float (*)[NE + 4])(smraw + BK * (TB + 4));
    float (*lg)[NE + 1] = (float (*)[NE + 1])smraw;   // 64*65 floats <= buffer

    const int tid = threadIdx.x;
    const int tb  = blockIdx.x * TB;           // first token of this block
    const int tr4 = (tid >> 4) * 4;            // token micro-tile base (0..60)
    const int tx4 = (tid & 15) * 4;            // expert micro-tile base (0..60)

    if (tid < NE) cnt_s[tid] = 0;

    const float4* x4 = (const float4*)x;
    const float4* w4 = (const float4*)w;

    ull acc[2][4];
    #pragma unroll
    for (int i = 0; i < 2; i++)
        #pragma unroll
        for (int j = 0; j < 4; j++) acc[i][j] = 0ull;

    for (int k0 = 0; k0 < HID; k0 += BK) {
        __syncthreads();   // previous inner-loop readers done
        // stage: 64 rows x 32 k (x tokens) + 64 rows x 32 k (w experts)
        #pragma unroll
        for (int j = 0; j < 2; j++) {
            int idx = tid + j * 256;
            int row = idx >> 3;       // 0..63
            int c4  = idx & 7;        // float4 column within chunk
            float4 v = x4[(size_t)(tb + row) * (HID / 4) + (k0 >> 2) + c4];
            xs[c4 * 4 + 0][row] = v.x; xs[c4 * 4 + 1][row] = v.y;
            xs[c4 * 4 + 2][row] = v.z; xs[c4 * 4 + 3][row] = v.w;
            float4 u = w4[(size_t)row * (HID / 4) + (k0 >> 2) + c4];
            ws[c4 * 4 + 0][row] = u.x; ws[c4 * 4 + 1][row] = u.y;
            ws[c4 * 4 + 2][row] = u.z; ws[c4 * 4 + 3][row] = u.w;
        }
        __syncthreads();

        #pragma unroll 8
        for (int kk = 0; kk < BK; kk++) {
            float4 a4 = *(const float4*)&xs[kk][tr4];
            float4 b4 = *(const float4*)&ws[kk][tx4];
            ull ap0 = pack2(a4.x, a4.y);   // tokens tr4+0, tr4+1
            ull ap1 = pack2(a4.z, a4.w);   // tokens tr4+2, tr4+3
            ull bb;
            bb = pack2(b4.x, b4.x); fma2(acc[0][0], ap0, bb); fma2(acc[1][0], ap1, bb);
            bb = pack2(b4.y, b4.y); fma2(acc[0][1], ap0, bb); fma2(acc[1][1], ap1, bb);
            bb = pack2(b4.z, b4.z); fma2(acc[0][2], ap0, bb); fma2(acc[1][2], ap1, bb);
            bb = pack2(b4.w, b4.w); fma2(acc[0][3], ap0, bb); fma2(acc[1][3], ap1, bb);
        }
    }

    // dump logits to smem (reuse the staging buffer)
    __syncthreads();
    #pragma unroll
    for (int tp = 0; tp < 2; tp++)
        #pragma unroll
        for (int e = 0; e < 4; e++) {
            float lo, hi;
            unpack2(acc[tp][e], lo, hi);
            lg[tr4 + 2 * tp + 0][tx4 + e] = lo;
            lg[tr4 + 2 * tp + 1][tx4 + e] = hi;
        }
    __syncthreads();

    // softmax + top-2 per token; one warp handles 8 tokens
    const int warp = tid >> 5, lane = tid & 31;
    const int b = blockIdx.x >> 6;   // 64 blocks per batch (S/TB = 64)
    float sum0 = 0.0f, sum1 = 0.0f;  // per-expert score sums (experts lane, lane+32)

    for (int i = 0; i < 8; i++) {
        int t = warp * 8 + i;
        float v0 = lg[t][lane], v1 = lg[t][lane + 32];
        float m = fmaxf(v0, v1);
        #pragma unroll
        for (int o = 16; o; o >>= 1) m = fmaxf(m, __shfl_xor_sync(0xffffffffu, m, o));
        float e0 = expf(v0 - m), e1 = expf(v1 - m);
        float z = e0 + e1;
        #pragma unroll
        for (int o = 16; o; o >>= 1) z += __shfl_xor_sync(0xffffffffu, z, o);
        float p0 = e0 / z, p1 = e1 / z;
        sum0 += p0; sum1 += p1;

        // local top2 (tie -> lower index, matching lax.top_k)
        float tv1, tv2; int ti1, ti2;
        if (p0 >= p1) { tv1 = p0; ti1 = lane;      tv2 = p1; ti2 = lane + 32; }
        else          { tv1 = p1; ti1 = lane + 32; tv2 = p0; ti2 = lane; }
        // butterfly merge of top2 pairs
        #pragma unroll
        for (int o = 16; o; o >>= 1) {
            float ov1 = __shfl_xor_sync(0xffffffffu, tv1, o);
            int   oi1 = __shfl_xor_sync(0xffffffffu, ti1, o);
            float ov2 = __shfl_xor_sync(0xffffffffu, tv2, o);
            int   oi2 = __shfl_xor_sync(0xffffffffu, ti2, o);
            bool obeats = (ov1 > tv1) || (ov1 == tv1 && oi1 < ti1);
            if (obeats) {
                float nv2; int ni2;
                bool mine2 = (tv1 > ov2) || (tv1 == ov2 && ti1 < oi2);
                if (mine2) { nv2 = tv1; ni2 = ti1; } else { nv2 = ov2; ni2 = oi2; }
                tv1 = ov1; ti1 = oi1; tv2 = nv2; ti2 = ni2;
            } else {
                bool beats2 = (ov1 > tv2) || (ov1 == tv2 && oi1 < ti2);
                if (beats2) { tv2 = ov1; ti2 = oi1; }
            }
        }

        if (lane == 0) {
            int gt = tb + t;
            out[2 * gt + 0] = (float)ti1;
            out[2 * gt + 1] = (float)ti2;
            float zz = tv1 + tv2 + 1e-20f;
            out[2 * NTOK + 2 * gt + 0] = tv1 / zz;
            out[2 * NTOK + 2 * gt + 1] = tv2 / zz;
            atomicAdd(&cnt_s[ti1], 1);
            atomicAdd(&cnt_s[ti2], 1);
        }
    }

    atomicAdd(&g_ssum[b * NE + lane],      sum0);
    atomicAdd(&g_ssum[b * NE + lane + 32], sum1);
    __syncthreads();
    if (tid < NE) atomicAdd(&g_cnt[b * NE + tid], cnt_s[tid]);
}

__global__ void aux_kernel(float* __restrict__ out) {
    int t = threadIdx.x;  // 256 = NBATCH*NE
    // ce = cnt / (S*K/E) ; mean_s scores = ssum / S
    float v = ((float)g_cnt[t] * ((float)NE / (float)(SEQ * TOPK))) *
              (g_ssum[t] / (float)SEQ);
    #pragma unroll
    for (int o = 16; o; o >>= 1) v += __shfl_xor_sync(0xffffffffu, v, o);
    __shared__ float wsum[8];
    if ((t & 31) == 0) wsum[t >> 5] = v;
    __syncthreads();
    if (t < 8) {
        float s = wsum[t];
        #pragma unroll
        for (int o = 4; o; o >>= 1) s += __shfl_xor_sync(0xffu, s, o);
        if (t == 0) out[4 * NTOK] = 0.01f * s / (float)NBATCH;
    }
}

extern "C" void kernel_launch(void* const* d_in, const int* in_sizes, int n_in,
                              void* d_out, int out_size) {
    const float* x = (const float*)d_in[0];   // hidden_states [4,4096,2048] f32
    const float* w = (const float*)d_in[1];   // weight        [64,2048]    f32
    float* out = (float*)d_out;               // [2T idx | 2T weight | aux]

    zero_acc_kernel<<<1, 256>>>();
    gate_kernel<<<NTOK / TB, 256>>>(x, w, out);
    aux_kernel<<<1, 256>>>(out);
}